// round 14
// baseline (speedup 1.0000x reference)
#include <cuda_runtime.h>
#include <cuda_bf16.h>
#include <cstdint>
#include <cmath>

static constexpr int Bn = 32, Tn = 2048, DIN = 1024, H1 = 512, H2 = 32;
static constexpr int Mrows = Bn * Tn;   // 65536

// Device scratch
__device__ __nv_bfloat16 g_w1b[DIN * H1];   // W1 bf16 [1024 k][512 n]
__device__ __nv_bfloat16 g_w2b[H1 * H2];    // W2 bf16 [512 k][32 n]
__device__ float         g_logits[Mrows];

// ---------------------------------------------------------------------------
// helpers (baseline PTX only)
// ---------------------------------------------------------------------------
__device__ __forceinline__ uint32_t smaddr(const void* p) {
    return (uint32_t)__cvta_generic_to_shared(p);
}
__device__ __forceinline__ void ldsm4(uint32_t addr, uint32_t& r0, uint32_t& r1,
                                      uint32_t& r2, uint32_t& r3) {
    asm volatile("ldmatrix.sync.aligned.m8n8.x4.shared.b16 {%0,%1,%2,%3}, [%4];"
                 : "=r"(r0), "=r"(r1), "=r"(r2), "=r"(r3) : "r"(addr));
}
__device__ __forceinline__ void ldsm4t(uint32_t addr, uint32_t& r0, uint32_t& r1,
                                       uint32_t& r2, uint32_t& r3) {
    asm volatile("ldmatrix.sync.aligned.m8n8.x4.trans.shared.b16 {%0,%1,%2,%3}, [%4];"
                 : "=r"(r0), "=r"(r1), "=r"(r2), "=r"(r3) : "r"(addr));
}
__device__ __forceinline__ void mma_bf16(float& c0, float& c1, float& c2, float& c3,
                                         uint32_t a0, uint32_t a1, uint32_t a2, uint32_t a3,
                                         uint32_t b0, uint32_t b1) {
    asm volatile("mma.sync.aligned.m16n8k16.row.col.f32.bf16.bf16.f32 "
                 "{%0,%1,%2,%3}, {%4,%5,%6,%7}, {%8,%9}, {%0,%1,%2,%3};"
                 : "+f"(c0), "+f"(c1), "+f"(c2), "+f"(c3)
                 : "r"(a0), "r"(a1), "r"(a2), "r"(a3), "r"(b0), "r"(b1));
}
__device__ __forceinline__ void cp16(uint32_t dst, const void* src) {
    asm volatile("cp.async.cg.shared.global [%0], [%1], 16;" :: "r"(dst), "l"(src));
}
__device__ __forceinline__ void cp_commit() { asm volatile("cp.async.commit_group;"); }
template <int N> __device__ __forceinline__ void cp_wait() {
    asm volatile("cp.async.wait_group %0;" :: "n"(N));
}

// ---------------------------------------------------------------------------
// smem layout (R5/R10-proven 3-stage)
// ---------------------------------------------------------------------------
static constexpr uint32_t A_STR_B  = 144;
static constexpr uint32_t B_STR_B  = 1040;
static constexpr uint32_t ABUF     = 0;
static constexpr uint32_t BBUF     = 9216;
static constexpr uint32_t STAGE_B  = 75776;
static constexpr uint32_t SMEM_TOTAL = 3 * STAGE_B;   // 227328
static constexpr uint32_t W2S_STR_B = 80;
static constexpr uint32_t W2S_OFF   = STAGE_B;
static constexpr uint32_t H2P_OFF   = STAGE_B + 40960;

// ---------------------------------------------------------------------------
// kernel 0: convert W1/W2 fp32 -> bf16 (132 fat blocks, 4 float4/thread)
// ---------------------------------------------------------------------------
__global__ void k_convert(const float* __restrict__ W1, const float* __restrict__ W2) {
    const int n1 = DIN * H1 / 4;     // 131072
    const int n2 = H1 * H2 / 4;      // 4096
    const int total = n1 + n2;       // 135168 = 132*256*4
    int base = blockIdx.x * blockDim.x + threadIdx.x;
    #pragma unroll
    for (int r = 0; r < 4; r++) {
        int g = base + r * 33792;    // 132*256
        if (g < n1) {
            float4 v = reinterpret_cast<const float4*>(W1)[g];
            __nv_bfloat162* p = reinterpret_cast<__nv_bfloat162*>(g_w1b) + g * 2;
            p[0] = __floats2bfloat162_rn(v.x, v.y);
            p[1] = __floats2bfloat162_rn(v.z, v.w);
        } else if (g < total) {
            int h = g - n1;
            float4 v = reinterpret_cast<const float4*>(W2)[h];
            __nv_bfloat162* p = reinterpret_cast<__nv_bfloat162*>(g_w2b) + h * 2;
            p[0] = __floats2bfloat162_rn(v.x, v.y);
            p[1] = __floats2bfloat162_rn(v.z, v.w);
        }
    }
}

// ---------------------------------------------------------------------------
// fused MLP: 1024 CTAs x 512 threads, M=64 N=512, k-slab 64, 3 stages
// unrolled mainloop (R13 winner) + parallel layer-3 epilogue
// ---------------------------------------------------------------------------
__global__ void __launch_bounds__(512, 1)
k_fused(const float* __restrict__ X, const float* __restrict__ b1,
        const float* __restrict__ b2, const float* __restrict__ W3,
        const float* __restrict__ b3, const int* __restrict__ seq_len) {
    // ragged skip: this CTA's 64 rows all beyond this sample's valid length?
    const int bsm = blockIdx.x >> 5;         // sample (2048/64 = 32 CTAs each)
    const int jt  = blockIdx.x & 31;         // tile within sample
    if (jt * 64 >= seq_len[bsm]) return;

    extern __shared__ char smem[];
    const uint32_t sb = smaddr(smem);
    const int tid  = threadIdx.x;
    const int lane = tid & 31;
    const int wid  = tid >> 5;
    const int wm   = wid >> 3;     // 0..1
    const int wn   = wid & 7;      // 0..7
    const int m0   = blockIdx.x * 64;

    const int lk   = lane & 15;
    const int lhi8 = (lane & 16) ? 8 : 0;

    const int am   = tid >> 3;     // A-stage row 0..63
    const int aks  = tid & 7;      // 8-float k-segment

    float c[2][8][4];
    #pragma unroll
    for (int mf = 0; mf < 2; mf++)
        #pragma unroll
        for (int t = 0; t < 8; t++)
            #pragma unroll
            for (int q = 0; q < 4; q++) c[mf][t][q] = 0.f;

    auto loadB = [&](int k0, uint32_t stage_off) {
        #pragma unroll
        for (int j = 0; j < 8; j++) {
            int i = tid + 512 * j;
            int kr = i >> 6, seg = i & 63;
            cp16(sb + stage_off + BBUF + (uint32_t)kr * B_STR_B + (uint32_t)seg * 16,
                 g_w1b + (size_t)(k0 + kr) * H1 + seg * 8);
        }
    };
    float4 xa, xb;
    auto loadA_regs = [&](int k0) {
        const float4* xp = reinterpret_cast<const float4*>(
            X + (size_t)(m0 + am) * DIN + k0 + aks * 8);
        xa = xp[0]; xb = xp[1];
    };
    auto stsA = [&](uint32_t stage_off) {
        __nv_bfloat162 p0 = __floats2bfloat162_rn(xa.x, xa.y);
        __nv_bfloat162 p1 = __floats2bfloat162_rn(xa.z, xa.w);
        __nv_bfloat162 p2 = __floats2bfloat162_rn(xb.x, xb.y);
        __nv_bfloat162 p3 = __floats2bfloat162_rn(xb.z, xb.w);
        uint4 v = make_uint4(*(uint32_t*)&p0, *(uint32_t*)&p1,
                             *(uint32_t*)&p2, *(uint32_t*)&p3);
        *reinterpret_cast<uint4*>(smem + stage_off + ABUF +
                                  (uint32_t)am * A_STR_B + (uint32_t)aks * 16) = v;
    };

    // ---- prologue: B(0), B(1) in flight; A(0) staged ----
    loadB(0, 0);
    cp_commit();
    loadB(64, STAGE_B);
    cp_commit();
    loadA_regs(0);
    stsA(0);
    cp_wait<1>();
    __syncthreads();

    // ---- mainloop: 16 k-slabs of 64, 3-stage ring, FULLY UNROLLED ----
    #pragma unroll
    for (int ks = 0; ks < 16; ks++) {
        const uint32_t cur = (uint32_t)(ks % 3) * STAGE_B;
        if (ks < 15) loadA_regs((ks + 1) * 64);
        if (ks < 14) {
            loadB((ks + 2) * 64, (uint32_t)((ks + 2) % 3) * STAGE_B);
            cp_commit();
        } else if (ks == 15) {
            #pragma unroll
            for (int j = 0; j < 4; j++) {
                int i = tid + 512 * j;
                int kr = i >> 2, seg = i & 3;
                cp16(sb + W2S_OFF + (uint32_t)kr * W2S_STR_B + (uint32_t)seg * 16,
                     g_w2b + (size_t)kr * H2 + seg * 8);
            }
            cp_commit();
        }

        const uint32_t abase = sb + cur + ABUF +
            (uint32_t)(wm * 32 + lk) * A_STR_B + (uint32_t)lhi8 * 2;
        const uint32_t bbase = sb + cur + BBUF +
            (uint32_t)lk * B_STR_B + (uint32_t)(wn * 64 + lhi8) * 2;

        #pragma unroll
        for (int st = 0; st < 4; st++) {
            uint32_t bb[4][4];
            #pragma unroll
            for (int p = 0; p < 4; p++)
                ldsm4t(bbase + (uint32_t)st * 16 * B_STR_B + (uint32_t)p * 32,
                       bb[p][0], bb[p][1], bb[p][2], bb[p][3]);
            #pragma unroll
            for (int mf = 0; mf < 2; mf++) {
                uint32_t a0, a1, a2, a3;
                ldsm4(abase + (uint32_t)mf * 16 * A_STR_B + (uint32_t)st * 32,
                      a0, a1, a2, a3);
                #pragma unroll
                for (int t = 0; t < 8; t++)
                    mma_bf16(c[mf][t][0], c[mf][t][1], c[mf][t][2], c[mf][t][3],
                             a0, a1, a2, a3,
                             bb[t >> 1][(t & 1) * 2], bb[t >> 1][(t & 1) * 2 + 1]);
            }
        }

        if (ks < 15) stsA((uint32_t)((ks + 1) % 3) * STAGE_B);
        if (ks < 14) cp_wait<1>();
        else         cp_wait<0>();
        __syncthreads();
    }

    // ---- epilogue ----
    float2 bias[8];
    #pragma unroll
    for (int t = 0; t < 8; t++)
        bias[t] = *reinterpret_cast<const float2*>(b1 + wn * 64 + t * 8 + (lane & 3) * 2);

    uint32_t a2f[2][4][4];
    #pragma unroll
    for (int mf = 0; mf < 2; mf++) {
        #pragma unroll
        for (int s = 0; s < 4; s++) {
            const int t0 = 2 * s, t1 = 2 * s + 1;
            __nv_bfloat162 h;
            h = __floats2bfloat162_rn(fmaxf(c[mf][t0][0] + bias[t0].x, 0.f),
                                      fmaxf(c[mf][t0][1] + bias[t0].y, 0.f));
            a2f[mf][s][0] = *(uint32_t*)&h;
            h = __floats2bfloat162_rn(fmaxf(c[mf][t0][2] + bias[t0].x, 0.f),
                                      fmaxf(c[mf][t0][3] + bias[t0].y, 0.f));
            a2f[mf][s][1] = *(uint32_t*)&h;
            h = __floats2bfloat162_rn(fmaxf(c[mf][t1][0] + bias[t1].x, 0.f),
                                      fmaxf(c[mf][t1][1] + bias[t1].y, 0.f));
            a2f[mf][s][2] = *(uint32_t*)&h;
            h = __floats2bfloat162_rn(fmaxf(c[mf][t1][2] + bias[t1].x, 0.f),
                                      fmaxf(c[mf][t1][3] + bias[t1].y, 0.f));
            a2f[mf][s][3] = *(uint32_t*)&h;
        }
    }

    float d2[2][4][4];
    #pragma unroll
    for (int mf = 0; mf < 2; mf++)
        #pragma unroll
        for (int nf = 0; nf < 4; nf++)
            #pragma unroll
            for (int q = 0; q < 4; q++) d2[mf][nf][q] = 0.f;

    #pragma unroll
    for (int s = 0; s < 4; s++) {
        uint32_t wb[2][4];
        #pragma unroll
        for (int nh = 0; nh < 2; nh++)
            ldsm4t(sb + W2S_OFF + (uint32_t)(wn * 64 + s * 16 + lk) * W2S_STR_B +
                       (uint32_t)(lhi8 + nh * 16) * 2,
                   wb[nh][0], wb[nh][1], wb[nh][2], wb[nh][3]);
        #pragma unroll
        for (int mf = 0; mf < 2; mf++)
            #pragma unroll
            for (int nf = 0; nf < 4; nf++)
                mma_bf16(d2[mf][nf][0], d2[mf][nf][1], d2[mf][nf][2], d2[mf][nf][3],
                         a2f[mf][s][0], a2f[mf][s][1], a2f[mf][s][2], a2f[mf][s][3],
                         wb[nf >> 1][(nf & 1) * 2], wb[nf >> 1][(nf & 1) * 2 + 1]);
    }

    float* H2p = reinterpret_cast<float*>(smem + H2P_OFF);
    #pragma unroll
    for (int mf = 0; mf < 2; mf++)
        #pragma unroll
        for (int nf = 0; nf < 4; nf++)
            #pragma unroll
            for (int q = 0; q < 4; q++) {
                int row = wm * 32 + mf * 16 + (lane >> 2) + ((q >= 2) ? 8 : 0);
                int col = nf * 8 + (lane & 3) * 2 + (q & 1);
                H2p[(row * 8 + wn) * 33 + col] = d2[mf][nf][q];
            }
    __syncthreads();

    // ---- parallel layer 3 + sigmoid: all 512 threads ----
    // acc = b3 + sum_j b2[j]*W3[j] + sum_w sum_j H2p[row][w][j]*W3[j]
    {
        const int row = tid >> 3;      // 0..63
        const int pw  = tid & 7;       // partial-w lane
        float s = 0.f;
        const float* hp = H2p + (row * 8 + pw) * 33;
        #pragma unroll
        for (int j = 0; j < H2; j++) s += hp[j] * W3[j];
        // fold 8 partials (pw bits are lane bits 0..2)
        #pragma unroll
        for (int o = 1; o < 8; o <<= 1)
            s += __shfl_xor_sync(0xFFFFFFFF, s, o);
        if (pw == 0) {
            float cb = 0.f;
            #pragma unroll
            for (int j = 0; j < H2; j++) cb += b2[j] * W3[j];
            float acc = b3[0] + cb + s;
            g_logits[m0 + row] = 1.0f / (1.0f + expf(-acc));
        }
    }
}

// ---------------------------------------------------------------------------
// top-k mean via MSB radix-select with PARALLEL suffix-scan digit search
// ---------------------------------------------------------------------------
__global__ void k_topk(const int* __restrict__ seq_len, float* __restrict__ out) {
    __shared__ uint32_t keys[Tn];
    __shared__ int      hist[256];
    __shared__ int      scan[257];
    __shared__ uint32_t sh_prefix;
    __shared__ int      sh_k;
    __shared__ float    redf[32];
    __shared__ int      redi[32];

    const int b = blockIdx.x;
    const int tid = threadIdx.x;
    const int lane = tid & 31;
    const int wrp  = tid >> 5;
    const int sl = seq_len[b];
    const int k = sl / 16 + 1;

    for (int i = tid; i < Tn; i += 256)
        keys[i] = (i < sl) ? __float_as_uint(g_logits[b * Tn + i]) : 0u;  // sigmoid>0
    if (tid == 0) { sh_prefix = 0u; sh_k = k; scan[256] = 0; }
    __syncthreads();

    #pragma unroll
    for (int pass = 0; pass < 4; pass++) {
        const int shift = 24 - pass * 8;
        const uint32_t mask_hi = (shift == 24) ? 0u : (0xFFFFFFFFu << (shift + 8));
        hist[tid] = 0;
        __syncthreads();
        const uint32_t pfx = sh_prefix;
        const int kc = sh_k;
        for (int i = tid; i < Tn; i += 256) {
            uint32_t key = keys[i];
            if ((key & mask_hi) == pfx)
                atomicAdd(&hist[(key >> shift) & 255], 1);
        }
        __syncthreads();
        scan[tid] = hist[tid];
        __syncthreads();
        #pragma unroll
        for (int off = 1; off < 256; off <<= 1) {
            int v = scan[tid] + ((tid + off < 256) ? scan[tid + off] : 0);
            __syncthreads();
            scan[tid] = v;
            __syncthreads();
        }
        if (scan[tid] >= kc && scan[tid + 1] < kc) {
            sh_k = kc - scan[tid + 1];
            sh_prefix = pfx | ((uint32_t)tid << shift);
        }
        __syncthreads();
    }

    const uint32_t t = sh_prefix;
    float s = 0.f; int cnt = 0;
    for (int i = tid; i < Tn; i += 256) {
        uint32_t key = keys[i];
        if (key > t) { s += __uint_as_float(key); cnt++; }
    }
    #pragma unroll
    for (int o = 16; o > 0; o >>= 1) {
        s   += __shfl_xor_sync(0xFFFFFFFF, s, o);
        cnt += __shfl_xor_sync(0xFFFFFFFF, cnt, o);
    }
    if (lane == 0) { redf[wrp] = s; redi[wrp] = cnt; }
    __syncthreads();
    if (tid == 0) {
        float st = 0.f; int ct = 0;
        #pragma unroll
        for (int w = 0; w < 8; w++) { st += redf[w]; ct += redi[w]; }
        out[b] = (st + (float)(k - ct) * __uint_as_float(t)) / (float)k;
    }
}

// ---------------------------------------------------------------------------
extern "C" void kernel_launch(void* const* d_in, const int* in_sizes, int n_in,
                              void* d_out, int out_size) {
    const float* X   = (const float*)d_in[0];
    const float* W1  = (const float*)d_in[1];
    const float* b1  = (const float*)d_in[2];
    const float* W2  = (const float*)d_in[3];
    const float* b2  = (const float*)d_in[4];
    const float* W3  = (const float*)d_in[5];
    const float* b3  = (const float*)d_in[6];
    const int*   seq = (const int*)d_in[7];
    float* out = (float*)d_out;

    k_convert<<<132, 256>>>(W1, W2);

    cudaFuncSetAttribute(k_fused, cudaFuncAttributeMaxDynamicSharedMemorySize, SMEM_TOTAL);
    k_fused<<<Mrows / 64, 512, SMEM_TOTAL>>>(X, b1, b2, W3, b3, seq);

    k_topk<<<Bn, 256>>>(seq, out);
}

// round 15
// speedup vs baseline: 1.1539x; 1.1539x over previous
#include <cuda_runtime.h>
#include <cuda_bf16.h>
#include <cstdint>
#include <cmath>

static constexpr int Bn = 32, Tn = 2048, DIN = 1024, H1 = 512, H2 = 32;
static constexpr int Mrows = Bn * Tn;   // 65536

// Device scratch
__device__ __nv_bfloat16 g_w1b[DIN * H1];   // W1 bf16 [1024 k][512 n]
__device__ __nv_bfloat16 g_w2b[H1 * H2];    // W2 bf16 [512 k][32 n]
__device__ float         g_logits[Mrows];

// ---------------------------------------------------------------------------
// helpers (baseline PTX only)
// ---------------------------------------------------------------------------
__device__ __forceinline__ uint32_t smaddr(const void* p) {
    return (uint32_t)__cvta_generic_to_shared(p);
}
__device__ __forceinline__ void ldsm4(uint32_t addr, uint32_t& r0, uint32_t& r1,
                                      uint32_t& r2, uint32_t& r3) {
    asm volatile("ldmatrix.sync.aligned.m8n8.x4.shared.b16 {%0,%1,%2,%3}, [%4];"
                 : "=r"(r0), "=r"(r1), "=r"(r2), "=r"(r3) : "r"(addr));
}
__device__ __forceinline__ void ldsm4t(uint32_t addr, uint32_t& r0, uint32_t& r1,
                                       uint32_t& r2, uint32_t& r3) {
    asm volatile("ldmatrix.sync.aligned.m8n8.x4.trans.shared.b16 {%0,%1,%2,%3}, [%4];"
                 : "=r"(r0), "=r"(r1), "=r"(r2), "=r"(r3) : "r"(addr));
}
__device__ __forceinline__ void mma_bf16(float& c0, float& c1, float& c2, float& c3,
                                         uint32_t a0, uint32_t a1, uint32_t a2, uint32_t a3,
                                         uint32_t b0, uint32_t b1) {
    asm volatile("mma.sync.aligned.m16n8k16.row.col.f32.bf16.bf16.f32 "
                 "{%0,%1,%2,%3}, {%4,%5,%6,%7}, {%8,%9}, {%0,%1,%2,%3};"
                 : "+f"(c0), "+f"(c1), "+f"(c2), "+f"(c3)
                 : "r"(a0), "r"(a1), "r"(a2), "r"(a3), "r"(b0), "r"(b1));
}
__device__ __forceinline__ void cp16(uint32_t dst, const void* src) {
    asm volatile("cp.async.cg.shared.global [%0], [%1], 16;" :: "r"(dst), "l"(src));
}
__device__ __forceinline__ void cp_commit() { asm volatile("cp.async.commit_group;"); }
template <int N> __device__ __forceinline__ void cp_wait() {
    asm volatile("cp.async.wait_group %0;" :: "n"(N));
}

// ---------------------------------------------------------------------------
// smem layout (R5/R10-proven 3-stage)
// ---------------------------------------------------------------------------
static constexpr uint32_t A_STR_B  = 144;
static constexpr uint32_t B_STR_B  = 1040;
static constexpr uint32_t ABUF     = 0;
static constexpr uint32_t BBUF     = 9216;
static constexpr uint32_t STAGE_B  = 75776;
static constexpr uint32_t SMEM_TOTAL = 3 * STAGE_B;   // 227328
static constexpr uint32_t W2S_STR_B = 80;
static constexpr uint32_t W2S_OFF   = STAGE_B;
static constexpr uint32_t H2P_OFF   = STAGE_B + 40960;

// ---------------------------------------------------------------------------
// kernel 0: convert W1/W2 fp32 -> bf16 device globals (R13-proven shape)
// ---------------------------------------------------------------------------
__global__ void k_convert(const float* __restrict__ W1, const float* __restrict__ W2) {
    int g = blockIdx.x * blockDim.x + threadIdx.x;
    const int n1 = DIN * H1 / 4;
    const int n2 = H1 * H2 / 4;
    if (g < n1) {
        float4 v = reinterpret_cast<const float4*>(W1)[g];
        __nv_bfloat162* p = reinterpret_cast<__nv_bfloat162*>(g_w1b) + g * 2;
        p[0] = __floats2bfloat162_rn(v.x, v.y);
        p[1] = __floats2bfloat162_rn(v.z, v.w);
    } else if (g - n1 < n2) {
        int h = g - n1;
        float4 v = reinterpret_cast<const float4*>(W2)[h];
        __nv_bfloat162* p = reinterpret_cast<__nv_bfloat162*>(g_w2b) + h * 2;
        p[0] = __floats2bfloat162_rn(v.x, v.y);
        p[1] = __floats2bfloat162_rn(v.z, v.w);
    }
}

// ---------------------------------------------------------------------------
// fused MLP: 1024 CTAs x 512 threads, M=64 N=512, k-slab 64, 3 stages
// R13 winner, byte-for-byte (unrolled mainloop + ragged skip)
// ---------------------------------------------------------------------------
__global__ void __launch_bounds__(512, 1)
k_fused(const float* __restrict__ X, const float* __restrict__ b1,
        const float* __restrict__ b2, const float* __restrict__ W3,
        const float* __restrict__ b3, const int* __restrict__ seq_len) {
    // ragged skip: this CTA's 64 rows all beyond this sample's valid length?
    const int bsm = blockIdx.x >> 5;         // sample (2048/64 = 32 CTAs each)
    const int jt  = blockIdx.x & 31;         // tile within sample
    if (jt * 64 >= seq_len[bsm]) return;

    extern __shared__ char smem[];
    const uint32_t sb = smaddr(smem);
    const int tid  = threadIdx.x;
    const int lane = tid & 31;
    const int wid  = tid >> 5;
    const int wm   = wid >> 3;     // 0..1
    const int wn   = wid & 7;      // 0..7
    const int m0   = blockIdx.x * 64;

    const int lk   = lane & 15;
    const int lhi8 = (lane & 16) ? 8 : 0;

    const int am   = tid >> 3;     // A-stage row 0..63
    const int aks  = tid & 7;      // 8-float k-segment

    float c[2][8][4];
    #pragma unroll
    for (int mf = 0; mf < 2; mf++)
        #pragma unroll
        for (int t = 0; t < 8; t++)
            #pragma unroll
            for (int q = 0; q < 4; q++) c[mf][t][q] = 0.f;

    auto loadB = [&](int k0, uint32_t stage_off) {
        #pragma unroll
        for (int j = 0; j < 8; j++) {
            int i = tid + 512 * j;
            int kr = i >> 6, seg = i & 63;
            cp16(sb + stage_off + BBUF + (uint32_t)kr * B_STR_B + (uint32_t)seg * 16,
                 g_w1b + (size_t)(k0 + kr) * H1 + seg * 8);
        }
    };
    float4 xa, xb;
    auto loadA_regs = [&](int k0) {
        const float4* xp = reinterpret_cast<const float4*>(
            X + (size_t)(m0 + am) * DIN + k0 + aks * 8);
        xa = xp[0]; xb = xp[1];
    };
    auto stsA = [&](uint32_t stage_off) {
        __nv_bfloat162 p0 = __floats2bfloat162_rn(xa.x, xa.y);
        __nv_bfloat162 p1 = __floats2bfloat162_rn(xa.z, xa.w);
        __nv_bfloat162 p2 = __floats2bfloat162_rn(xb.x, xb.y);
        __nv_bfloat162 p3 = __floats2bfloat162_rn(xb.z, xb.w);
        uint4 v = make_uint4(*(uint32_t*)&p0, *(uint32_t*)&p1,
                             *(uint32_t*)&p2, *(uint32_t*)&p3);
        *reinterpret_cast<uint4*>(smem + stage_off + ABUF +
                                  (uint32_t)am * A_STR_B + (uint32_t)aks * 16) = v;
    };

    // ---- prologue: B(0), B(1) in flight; A(0) staged ----
    loadB(0, 0);
    cp_commit();
    loadB(64, STAGE_B);
    cp_commit();
    loadA_regs(0);
    stsA(0);
    cp_wait<1>();
    __syncthreads();

    // ---- mainloop: 16 k-slabs of 64, 3-stage ring, FULLY UNROLLED ----
    #pragma unroll
    for (int ks = 0; ks < 16; ks++) {
        const uint32_t cur = (uint32_t)(ks % 3) * STAGE_B;
        if (ks < 15) loadA_regs((ks + 1) * 64);
        if (ks < 14) {
            loadB((ks + 2) * 64, (uint32_t)((ks + 2) % 3) * STAGE_B);
            cp_commit();
        } else if (ks == 15) {
            #pragma unroll
            for (int j = 0; j < 4; j++) {
                int i = tid + 512 * j;
                int kr = i >> 2, seg = i & 3;
                cp16(sb + W2S_OFF + (uint32_t)kr * W2S_STR_B + (uint32_t)seg * 16,
                     g_w2b + (size_t)kr * H2 + seg * 8);
            }
            cp_commit();
        }

        const uint32_t abase = sb + cur + ABUF +
            (uint32_t)(wm * 32 + lk) * A_STR_B + (uint32_t)lhi8 * 2;
        const uint32_t bbase = sb + cur + BBUF +
            (uint32_t)lk * B_STR_B + (uint32_t)(wn * 64 + lhi8) * 2;

        #pragma unroll
        for (int st = 0; st < 4; st++) {
            uint32_t bb[4][4];
            #pragma unroll
            for (int p = 0; p < 4; p++)
                ldsm4t(bbase + (uint32_t)st * 16 * B_STR_B + (uint32_t)p * 32,
                       bb[p][0], bb[p][1], bb[p][2], bb[p][3]);
            #pragma unroll
            for (int mf = 0; mf < 2; mf++) {
                uint32_t a0, a1, a2, a3;
                ldsm4(abase + (uint32_t)mf * 16 * A_STR_B + (uint32_t)st * 32,
                      a0, a1, a2, a3);
                #pragma unroll
                for (int t = 0; t < 8; t++)
                    mma_bf16(c[mf][t][0], c[mf][t][1], c[mf][t][2], c[mf][t][3],
                             a0, a1, a2, a3,
                             bb[t >> 1][(t & 1) * 2], bb[t >> 1][(t & 1) * 2 + 1]);
            }
        }

        if (ks < 15) stsA((uint32_t)((ks + 1) % 3) * STAGE_B);
        if (ks < 14) cp_wait<1>();
        else         cp_wait<0>();
        __syncthreads();
    }

    // ---- epilogue ----
    float2 bias[8];
    #pragma unroll
    for (int t = 0; t < 8; t++)
        bias[t] = *reinterpret_cast<const float2*>(b1 + wn * 64 + t * 8 + (lane & 3) * 2);

    uint32_t a2f[2][4][4];
    #pragma unroll
    for (int mf = 0; mf < 2; mf++) {
        #pragma unroll
        for (int s = 0; s < 4; s++) {
            const int t0 = 2 * s, t1 = 2 * s + 1;
            __nv_bfloat162 h;
            h = __floats2bfloat162_rn(fmaxf(c[mf][t0][0] + bias[t0].x, 0.f),
                                      fmaxf(c[mf][t0][1] + bias[t0].y, 0.f));
            a2f[mf][s][0] = *(uint32_t*)&h;
            h = __floats2bfloat162_rn(fmaxf(c[mf][t0][2] + bias[t0].x, 0.f),
                                      fmaxf(c[mf][t0][3] + bias[t0].y, 0.f));
            a2f[mf][s][1] = *(uint32_t*)&h;
            h = __floats2bfloat162_rn(fmaxf(c[mf][t1][0] + bias[t1].x, 0.f),
                                      fmaxf(c[mf][t1][1] + bias[t1].y, 0.f));
            a2f[mf][s][2] = *(uint32_t*)&h;
            h = __floats2bfloat162_rn(fmaxf(c[mf][t1][2] + bias[t1].x, 0.f),
                                      fmaxf(c[mf][t1][3] + bias[t1].y, 0.f));
            a2f[mf][s][3] = *(uint32_t*)&h;
        }
    }

    float d2[2][4][4];
    #pragma unroll
    for (int mf = 0; mf < 2; mf++)
        #pragma unroll
        for (int nf = 0; nf < 4; nf++)
            #pragma unroll
            for (int q = 0; q < 4; q++) d2[mf][nf][q] = 0.f;

    #pragma unroll
    for (int s = 0; s < 4; s++) {
        uint32_t wb[2][4];
        #pragma unroll
        for (int nh = 0; nh < 2; nh++)
            ldsm4t(sb + W2S_OFF + (uint32_t)(wn * 64 + s * 16 + lk) * W2S_STR_B +
                       (uint32_t)(lhi8 + nh * 16) * 2,
                   wb[nh][0], wb[nh][1], wb[nh][2], wb[nh][3]);
        #pragma unroll
        for (int mf = 0; mf < 2; mf++)
            #pragma unroll
            for (int nf = 0; nf < 4; nf++)
                mma_bf16(d2[mf][nf][0], d2[mf][nf][1], d2[mf][nf][2], d2[mf][nf][3],
                         a2f[mf][s][0], a2f[mf][s][1], a2f[mf][s][2], a2f[mf][s][3],
                         wb[nf >> 1][(nf & 1) * 2], wb[nf >> 1][(nf & 1) * 2 + 1]);
    }

    float* H2p = reinterpret_cast<float*>(smem + H2P_OFF);
    #pragma unroll
    for (int mf = 0; mf < 2; mf++)
        #pragma unroll
        for (int nf = 0; nf < 4; nf++)
            #pragma unroll
            for (int q = 0; q < 4; q++) {
                int row = wm * 32 + mf * 16 + (lane >> 2) + ((q >= 2) ? 8 : 0);
                int col = nf * 8 + (lane & 3) * 2 + (q & 1);
                H2p[(row * 8 + wn) * 33 + col] = d2[mf][nf][q];
            }
    __syncthreads();

    if (tid < 64) {
        float acc = b3[0];
        #pragma unroll
        for (int j = 0; j < H2; j++) {
            float s = 0.f;
            #pragma unroll
            for (int w = 0; w < 8; w++) s += H2p[(tid * 8 + w) * 33 + j];
            acc += (s + b2[j]) * W3[j];
        }
        g_logits[m0 + tid] = 1.0f / (1.0f + expf(-acc));
    }
}

// ---------------------------------------------------------------------------
// top-k mean via MSB radix-select, 512 threads (R10-validated body)
// ---------------------------------------------------------------------------
__global__ void k_topk(const int* __restrict__ seq_len, float* __restrict__ out) {
    __shared__ uint32_t keys[Tn];
    __shared__ int      hist[256];
    __shared__ int      scan[257];
    __shared__ uint32_t sh_prefix;
    __shared__ int      sh_k;
    __shared__ float    redf[16];
    __shared__ int      redi[16];

    const int b = blockIdx.x;
    const int tid = threadIdx.x;
    const int lane = tid & 31;
    const int wrp  = tid >> 5;
    const int sl = seq_len[b];
    const int k = sl / 16 + 1;

    for (int i = tid; i < Tn; i += 512)
        keys[i] = (i < sl) ? __float_as_uint(g_logits[b * Tn + i]) : 0u;  // sigmoid>0
    if (tid == 0) { sh_prefix = 0u; sh_k = k; scan[256] = 0; }
    __syncthreads();

    #pragma unroll
    for (int pass = 0; pass < 4; pass++) {
        const int shift = 24 - pass * 8;
        const uint32_t mask_hi = (shift == 24) ? 0u : (0xFFFFFFFFu << (shift + 8));
        if (tid < 256) hist[tid] = 0;
        __syncthreads();
        const uint32_t pfx = sh_prefix;
        const int kc = sh_k;
        for (int i = tid; i < Tn; i += 512) {
            uint32_t key = keys[i];
            if ((key & mask_hi) == pfx)
                atomicAdd(&hist[(key >> shift) & 255], 1);
        }
        __syncthreads();
        if (tid < 256) scan[tid] = hist[tid];
        __syncthreads();
        #pragma unroll
        for (int off = 1; off < 256; off <<= 1) {
            int v = 0;
            if (tid < 256) v = scan[tid] + ((tid + off < 256) ? scan[tid + off] : 0);
            __syncthreads();
            if (tid < 256) scan[tid] = v;
            __syncthreads();
        }
        if (tid < 256 && scan[tid] >= kc && scan[tid + 1] < kc) {
            sh_k = kc - scan[tid + 1];
            sh_prefix = pfx | ((uint32_t)tid << shift);
        }
        __syncthreads();
    }

    const uint32_t t = sh_prefix;         // exact k-th largest key
    float s = 0.f; int cnt = 0;
    for (int i = tid; i < Tn; i += 512) {
        uint32_t key = keys[i];
        if (key > t) { s += __uint_as_float(key); cnt++; }
    }
    #pragma unroll
    for (int o = 16; o > 0; o >>= 1) {
        s   += __shfl_xor_sync(0xFFFFFFFF, s, o);
        cnt += __shfl_xor_sync(0xFFFFFFFF, cnt, o);
    }
    if (lane == 0) { redf[wrp] = s; redi[wrp] = cnt; }
    __syncthreads();
    if (tid == 0) {
        float st = 0.f; int ct = 0;
        #pragma unroll
        for (int w = 0; w < 16; w++) { st += redf[w]; ct += redi[w]; }
        out[b] = (st + (float)(k - ct) * __uint_as_float(t)) / (float)k;
    }
}

// ---------------------------------------------------------------------------
extern "C" void kernel_launch(void* const* d_in, const int* in_sizes, int n_in,
                              void* d_out, int out_size) {
    const float* X   = (const float*)d_in[0];
    const float* W1  = (const float*)d_in[1];
    const float* b1  = (const float*)d_in[2];
    const float* W2  = (const float*)d_in[3];
    const float* b2  = (const float*)d_in[4];
    const float* W3  = (const float*)d_in[5];
    const float* b3  = (const float*)d_in[6];
    const int*   seq = (const int*)d_in[7];
    float* out = (float*)d_out;

    k_convert<<<(DIN * H1 / 4 + H1 * H2 / 4 + 255) / 256, 256>>>(W1, W2);

    cudaFuncSetAttribute(k_fused, cudaFuncAttributeMaxDynamicSharedMemorySize, SMEM_TOTAL);
    k_fused<<<Mrows / 64, 512, SMEM_TOTAL>>>(X, b1, b2, W3, b3, seq);

    k_topk<<<Bn, 512>>>(seq, out);
}

// round 16
// speedup vs baseline: 1.1673x; 1.0116x over previous
#include <cuda_runtime.h>
#include <cuda_bf16.h>
#include <cstdint>
#include <cmath>

static constexpr int Bn = 32, Tn = 2048, DIN = 1024, H1 = 512, H2 = 32;
static constexpr int Mrows = Bn * Tn;   // 65536

// Device scratch
__device__ __nv_bfloat16 g_w1b[DIN * H1];   // W1 bf16 [1024 k][512 n]
__device__ __nv_bfloat16 g_w2b[H1 * H2];    // W2 bf16 [512 k][32 n]
__device__ float         g_logits[Mrows];

// ---------------------------------------------------------------------------
// helpers (baseline PTX only)
// ---------------------------------------------------------------------------
__device__ __forceinline__ uint32_t smaddr(const void* p) {
    return (uint32_t)__cvta_generic_to_shared(p);
}
__device__ __forceinline__ void ldsm4(uint32_t addr, uint32_t& r0, uint32_t& r1,
                                      uint32_t& r2, uint32_t& r3) {
    asm volatile("ldmatrix.sync.aligned.m8n8.x4.shared.b16 {%0,%1,%2,%3}, [%4];"
                 : "=r"(r0), "=r"(r1), "=r"(r2), "=r"(r3) : "r"(addr));
}
__device__ __forceinline__ void ldsm4t(uint32_t addr, uint32_t& r0, uint32_t& r1,
                                       uint32_t& r2, uint32_t& r3) {
    asm volatile("ldmatrix.sync.aligned.m8n8.x4.trans.shared.b16 {%0,%1,%2,%3}, [%4];"
                 : "=r"(r0), "=r"(r1), "=r"(r2), "=r"(r3) : "r"(addr));
}
__device__ __forceinline__ void mma_bf16(float& c0, float& c1, float& c2, float& c3,
                                         uint32_t a0, uint32_t a1, uint32_t a2, uint32_t a3,
                                         uint32_t b0, uint32_t b1) {
    asm volatile("mma.sync.aligned.m16n8k16.row.col.f32.bf16.bf16.f32 "
                 "{%0,%1,%2,%3}, {%4,%5,%6,%7}, {%8,%9}, {%0,%1,%2,%3};"
                 : "+f"(c0), "+f"(c1), "+f"(c2), "+f"(c3)
                 : "r"(a0), "r"(a1), "r"(a2), "r"(a3), "r"(b0), "r"(b1));
}
__device__ __forceinline__ void cp16(uint32_t dst, const void* src) {
    asm volatile("cp.async.cg.shared.global [%0], [%1], 16;" :: "r"(dst), "l"(src));
}
__device__ __forceinline__ void cp_commit() { asm volatile("cp.async.commit_group;"); }
template <int N> __device__ __forceinline__ void cp_wait() {
    asm volatile("cp.async.wait_group %0;" :: "n"(N));
}

// ---------------------------------------------------------------------------
// smem layout (3-stage ring; epilogue overlays stage-1 region)
// ---------------------------------------------------------------------------
static constexpr uint32_t A_STR_B  = 144;
static constexpr uint32_t B_STR_B  = 1040;
static constexpr uint32_t ABUF     = 0;
static constexpr uint32_t BBUF     = 9216;
static constexpr uint32_t STAGE_B  = 75776;
static constexpr uint32_t SMEM_TOTAL = 3 * STAGE_B;   // 227328
static constexpr uint32_t W2S_STR_B = 80;
static constexpr uint32_t W2S_OFF   = STAGE_B;
static constexpr uint32_t H2P_OFF   = STAGE_B + 40960;

// ---------------------------------------------------------------------------
// kernel 0: convert W1/W2 fp32 -> bf16 device globals
// ---------------------------------------------------------------------------
__global__ void k_convert(const float* __restrict__ W1, const float* __restrict__ W2) {
    int g = blockIdx.x * blockDim.x + threadIdx.x;
    const int n1 = DIN * H1 / 4;
    const int n2 = H1 * H2 / 4;
    if (g < n1) {
        float4 v = reinterpret_cast<const float4*>(W1)[g];
        __nv_bfloat162* p = reinterpret_cast<__nv_bfloat162*>(g_w1b) + g * 2;
        p[0] = __floats2bfloat162_rn(v.x, v.y);
        p[1] = __floats2bfloat162_rn(v.z, v.w);
    } else if (g - n1 < n2) {
        int h = g - n1;
        float4 v = reinterpret_cast<const float4*>(W2)[h];
        __nv_bfloat162* p = reinterpret_cast<__nv_bfloat162*>(g_w2b) + h * 2;
        p[0] = __floats2bfloat162_rn(v.x, v.y);
        p[1] = __floats2bfloat162_rn(v.z, v.w);
    }
}

// ---------------------------------------------------------------------------
// fused MLP: 1024 CTAs x 512 threads, M=64 N=512, k-slab 64, 3 stages,
// fully-unrolled mainloop, ragged early-exit on seq_len
// ---------------------------------------------------------------------------
__global__ void __launch_bounds__(512, 1)
k_fused(const float* __restrict__ X, const float* __restrict__ b1,
        const float* __restrict__ b2, const float* __restrict__ W3,
        const float* __restrict__ b3, const int* __restrict__ seq_len) {
    // ragged skip: this CTA's 64 rows all beyond this sample's valid length?
    const int bsm = blockIdx.x >> 5;         // sample (2048/64 = 32 CTAs each)
    const int jt  = blockIdx.x & 31;         // tile within sample
    if (jt * 64 >= seq_len[bsm]) return;

    extern __shared__ char smem[];
    const uint32_t sb = smaddr(smem);
    const int tid  = threadIdx.x;
    const int lane = tid & 31;
    const int wid  = tid >> 5;
    const int wm   = wid >> 3;     // 0..1
    const int wn   = wid & 7;      // 0..7
    const int m0   = blockIdx.x * 64;

    const int lk   = lane & 15;
    const int lhi8 = (lane & 16) ? 8 : 0;

    const int am   = tid >> 3;     // A-stage row 0..63
    const int aks  = tid & 7;      // 8-float k-segment

    float c[2][8][4];
    #pragma unroll
    for (int mf = 0; mf < 2; mf++)
        #pragma unroll
        for (int t = 0; t < 8; t++)
            #pragma unroll
            for (int q = 0; q < 4; q++) c[mf][t][q] = 0.f;

    auto loadB = [&](int k0, uint32_t stage_off) {
        #pragma unroll
        for (int j = 0; j < 8; j++) {
            int i = tid + 512 * j;
            int kr = i >> 6, seg = i & 63;
            cp16(sb + stage_off + BBUF + (uint32_t)kr * B_STR_B + (uint32_t)seg * 16,
                 g_w1b + (size_t)(k0 + kr) * H1 + seg * 8);
        }
    };
    float4 xa, xb;
    auto loadA_regs = [&](int k0) {
        const float4* xp = reinterpret_cast<const float4*>(
            X + (size_t)(m0 + am) * DIN + k0 + aks * 8);
        xa = xp[0]; xb = xp[1];
    };
    auto stsA = [&](uint32_t stage_off) {
        __nv_bfloat162 p0 = __floats2bfloat162_rn(xa.x, xa.y);
        __nv_bfloat162 p1 = __floats2bfloat162_rn(xa.z, xa.w);
        __nv_bfloat162 p2 = __floats2bfloat162_rn(xb.x, xb.y);
        __nv_bfloat162 p3 = __floats2bfloat162_rn(xb.z, xb.w);
        uint4 v = make_uint4(*(uint32_t*)&p0, *(uint32_t*)&p1,
                             *(uint32_t*)&p2, *(uint32_t*)&p3);
        *reinterpret_cast<uint4*>(smem + stage_off + ABUF +
                                  (uint32_t)am * A_STR_B + (uint32_t)aks * 16) = v;
    };

    // ---- prologue: B(0), B(1) in flight; A(0) staged ----
    loadB(0, 0);
    cp_commit();
    loadB(64, STAGE_B);
    cp_commit();
    loadA_regs(0);
    stsA(0);
    cp_wait<1>();
    __syncthreads();

    // ---- mainloop: 16 k-slabs of 64, 3-stage ring, FULLY UNROLLED ----
    #pragma unroll
    for (int ks = 0; ks < 16; ks++) {
        const uint32_t cur = (uint32_t)(ks % 3) * STAGE_B;
        if (ks < 15) loadA_regs((ks + 1) * 64);
        if (ks < 14) {
            loadB((ks + 2) * 64, (uint32_t)((ks + 2) % 3) * STAGE_B);
            cp_commit();
        } else if (ks == 15) {
            #pragma unroll
            for (int j = 0; j < 4; j++) {
                int i = tid + 512 * j;
                int kr = i >> 2, seg = i & 3;
                cp16(sb + W2S_OFF + (uint32_t)kr * W2S_STR_B + (uint32_t)seg * 16,
                     g_w2b + (size_t)kr * H2 + seg * 8);
            }
            cp_commit();
        }

        const uint32_t abase = sb + cur + ABUF +
            (uint32_t)(wm * 32 + lk) * A_STR_B + (uint32_t)lhi8 * 2;
        const uint32_t bbase = sb + cur + BBUF +
            (uint32_t)lk * B_STR_B + (uint32_t)(wn * 64 + lhi8) * 2;

        #pragma unroll
        for (int st = 0; st < 4; st++) {
            uint32_t bb[4][4];
            #pragma unroll
            for (int p = 0; p < 4; p++)
                ldsm4t(bbase + (uint32_t)st * 16 * B_STR_B + (uint32_t)p * 32,
                       bb[p][0], bb[p][1], bb[p][2], bb[p][3]);
            #pragma unroll
            for (int mf = 0; mf < 2; mf++) {
                uint32_t a0, a1, a2, a3;
                ldsm4(abase + (uint32_t)mf * 16 * A_STR_B + (uint32_t)st * 32,
                      a0, a1, a2, a3);
                #pragma unroll
                for (int t = 0; t < 8; t++)
                    mma_bf16(c[mf][t][0], c[mf][t][1], c[mf][t][2], c[mf][t][3],
                             a0, a1, a2, a3,
                             bb[t >> 1][(t & 1) * 2], bb[t >> 1][(t & 1) * 2 + 1]);
            }
        }

        if (ks < 15) stsA((uint32_t)((ks + 1) % 3) * STAGE_B);
        if (ks < 14) cp_wait<1>();
        else         cp_wait<0>();
        __syncthreads();
    }

    // ---- epilogue ----
    float2 bias[8];
    #pragma unroll
    for (int t = 0; t < 8; t++)
        bias[t] = *reinterpret_cast<const float2*>(b1 + wn * 64 + t * 8 + (lane & 3) * 2);

    uint32_t a2f[2][4][4];
    #pragma unroll
    for (int mf = 0; mf < 2; mf++) {
        #pragma unroll
        for (int s = 0; s < 4; s++) {
            const int t0 = 2 * s, t1 = 2 * s + 1;
            __nv_bfloat162 h;
            h = __floats2bfloat162_rn(fmaxf(c[mf][t0][0] + bias[t0].x, 0.f),
                                      fmaxf(c[mf][t0][1] + bias[t0].y, 0.f));
            a2f[mf][s][0] = *(uint32_t*)&h;
            h = __floats2bfloat162_rn(fmaxf(c[mf][t0][2] + bias[t0].x, 0.f),
                                      fmaxf(c[mf][t0][3] + bias[t0].y, 0.f));
            a2f[mf][s][1] = *(uint32_t*)&h;
            h = __floats2bfloat162_rn(fmaxf(c[mf][t1][0] + bias[t1].x, 0.f),
                                      fmaxf(c[mf][t1][1] + bias[t1].y, 0.f));
            a2f[mf][s][2] = *(uint32_t*)&h;
            h = __floats2bfloat162_rn(fmaxf(c[mf][t1][2] + bias[t1].x, 0.f),
                                      fmaxf(c[mf][t1][3] + bias[t1].y, 0.f));
            a2f[mf][s][3] = *(uint32_t*)&h;
        }
    }

    float d2[2][4][4];
    #pragma unroll
    for (int mf = 0; mf < 2; mf++)
        #pragma unroll
        for (int nf = 0; nf < 4; nf++)
            #pragma unroll
            for (int q = 0; q < 4; q++) d2[mf][nf][q] = 0.f;

    #pragma unroll
    for (int s = 0; s < 4; s++) {
        uint32_t wb[2][4];
        #pragma unroll
        for (int nh = 0; nh < 2; nh++)
            ldsm4t(sb + W2S_OFF + (uint32_t)(wn * 64 + s * 16 + lk) * W2S_STR_B +
                       (uint32_t)(lhi8 + nh * 16) * 2,
                   wb[nh][0], wb[nh][1], wb[nh][2], wb[nh][3]);
        #pragma unroll
        for (int mf = 0; mf < 2; mf++)
            #pragma unroll
            for (int nf = 0; nf < 4; nf++)
                mma_bf16(d2[mf][nf][0], d2[mf][nf][1], d2[mf][nf][2], d2[mf][nf][3],
                         a2f[mf][s][0], a2f[mf][s][1], a2f[mf][s][2], a2f[mf][s][3],
                         wb[nf >> 1][(nf & 1) * 2], wb[nf >> 1][(nf & 1) * 2 + 1]);
    }

    float* H2p = reinterpret_cast<float*>(smem + H2P_OFF);
    #pragma unroll
    for (int mf = 0; mf < 2; mf++)
        #pragma unroll
        for (int nf = 0; nf < 4; nf++)
            #pragma unroll
            for (int q = 0; q < 4; q++) {
                int row = wm * 32 + mf * 16 + (lane >> 2) + ((q >= 2) ? 8 : 0);
                int col = nf * 8 + (lane & 3) * 2 + (q & 1);
                H2p[(row * 8 + wn) * 33 + col] = d2[mf][nf][q];
            }
    __syncthreads();

    if (tid < 64) {
        float acc = b3[0];
        #pragma unroll
        for (int j = 0; j < H2; j++) {
            float s = 0.f;
            #pragma unroll
            for (int w = 0; w < 8; w++) s += H2p[(tid * 8 + w) * 33 + j];
            acc += (s + b2[j]) * W3[j];
        }
        g_logits[m0 + tid] = 1.0f / (1.0f + expf(-acc));
    }
}

// ---------------------------------------------------------------------------
// top-k mean via MSB radix-select, 512 threads, parallel suffix-scan
// ---------------------------------------------------------------------------
__global__ void k_topk(const int* __restrict__ seq_len, float* __restrict__ out) {
    __shared__ uint32_t keys[Tn];
    __shared__ int      hist[256];
    __shared__ int      scan[257];
    __shared__ uint32_t sh_prefix;
    __shared__ int      sh_k;
    __shared__ float    redf[16];
    __shared__ int      redi[16];

    const int b = blockIdx.x;
    const int tid = threadIdx.x;
    const int lane = tid & 31;
    const int wrp  = tid >> 5;
    const int sl = seq_len[b];
    const int k = sl / 16 + 1;

    for (int i = tid; i < Tn; i += 512)
        keys[i] = (i < sl) ? __float_as_uint(g_logits[b * Tn + i]) : 0u;  // sigmoid>0
    if (tid == 0) { sh_prefix = 0u; sh_k = k; scan[256] = 0; }
    __syncthreads();

    #pragma unroll
    for (int pass = 0; pass < 4; pass++) {
        const int shift = 24 - pass * 8;
        const uint32_t mask_hi = (shift == 24) ? 0u : (0xFFFFFFFFu << (shift + 8));
        if (tid < 256) hist[tid] = 0;
        __syncthreads();
        const uint32_t pfx = sh_prefix;
        const int kc = sh_k;
        for (int i = tid; i < Tn; i += 512) {
            uint32_t key = keys[i];
            if ((key & mask_hi) == pfx)
                atomicAdd(&hist[(key >> shift) & 255], 1);
        }
        __syncthreads();
        if (tid < 256) scan[tid] = hist[tid];
        __syncthreads();
        #pragma unroll
        for (int off = 1; off < 256; off <<= 1) {
            int v = 0;
            if (tid < 256) v = scan[tid] + ((tid + off < 256) ? scan[tid + off] : 0);
            __syncthreads();
            if (tid < 256) scan[tid] = v;
            __syncthreads();
        }
        if (tid < 256 && scan[tid] >= kc && scan[tid + 1] < kc) {
            sh_k = kc - scan[tid + 1];
            sh_prefix = pfx | ((uint32_t)tid << shift);
        }
        __syncthreads();
    }

    const uint32_t t = sh_prefix;         // exact k-th largest key
    float s = 0.f; int cnt = 0;
    for (int i = tid; i < Tn; i += 512) {
        uint32_t key = keys[i];
        if (key > t) { s += __uint_as_float(key); cnt++; }
    }
    #pragma unroll
    for (int o = 16; o > 0; o >>= 1) {
        s   += __shfl_xor_sync(0xFFFFFFFF, s, o);
        cnt += __shfl_xor_sync(0xFFFFFFFF, cnt, o);
    }
    if (lane == 0) { redf[wrp] = s; redi[wrp] = cnt; }
    __syncthreads();
    if (tid == 0) {
        float st = 0.f; int ct = 0;
        #pragma unroll
        for (int w = 0; w < 16; w++) { st += redf[w]; ct += redi[w]; }
        out[b] = (st + (float)(k - ct) * __uint_as_float(t)) / (float)k;
    }
}

// ---------------------------------------------------------------------------
extern "C" void kernel_launch(void* const* d_in, const int* in_sizes, int n_in,
                              void* d_out, int out_size) {
    const float* X   = (const float*)d_in[0];
    const float* W1  = (const float*)d_in[1];
    const float* b1  = (const float*)d_in[2];
    const float* W2  = (const float*)d_in[3];
    const float* b2  = (const float*)d_in[4];
    const float* W3  = (const float*)d_in[5];
    const float* b3  = (const float*)d_in[6];
    const int*   seq = (const int*)d_in[7];
    float* out = (float*)d_out;

    k_convert<<<(DIN * H1 / 4 + H1 * H2 / 4 + 255) / 256, 256>>>(W1, W2);

    cudaFuncSetAttribute(k_fused, cudaFuncAttributeMaxDynamicSharedMemorySize, SMEM_TOTAL);
    k_fused<<<Mrows / 64, 512, SMEM_TOTAL>>>(X, b1, b2, W3, b3, seq);

    k_topk<<<Bn, 512>>>(seq, out);
}